// round 4
// baseline (speedup 1.0000x reference)
#include <cuda_runtime.h>
#include <math.h>

#define Bsz 1024
#define INd 256
#define Hd  512
#define Pd  128

// ---------------- scratch (no allocations allowed) ----------------
__device__ float g_h0[Bsz * Hd];
__device__ float g_h1[Bsz * Hd];
__device__ float g_q [Bsz * Hd];
__device__ float g_k [Bsz * Hd];
__device__ float g_v [Bsz * Hd];

// ---------------- helpers ----------------
__device__ __forceinline__ float ex2f(float x) {
    float y;
    asm("ex2.approx.f32 %0, %1;" : "=f"(y) : "f"(x));
    return y;
}

// ---------------- GEMM: C[M,N] = A[M,K] @ W[N,K]^T + bias ----------------
// Optional fused epilogue: C = res + gelu_exact(acc + bias)
struct GemmArgs {
    const float* A;
    const float* W[3];
    const float* bias[3];
    const float* res;
    float*       C[3];
    int M, N, K;
};

constexpr int BM = 64, BN = 64, BK = 16;

template <int FUSE_GELU>
__global__ __launch_bounds__(256) void gemm_kernel(GemmArgs g) {
    const int z = blockIdx.z;
    const float* __restrict__ A    = g.A;
    const float* __restrict__ W    = g.W[z];
    const float* __restrict__ bias = g.bias[z];
    float* __restrict__ C          = g.C[z];
    const int N = g.N, K = g.K;

    __shared__ float As[BK][BM + 4];
    __shared__ float Ws[BK][BN + 4];

    const int tid = threadIdx.x;
    const int tx = tid & 15;        // n-dir
    const int ty = tid >> 4;        // m-dir
    const int m0 = blockIdx.y * BM;
    const int n0 = blockIdx.x * BN;

    const int lr = tid >> 2;        // 0..63 : row within tile
    const int lk = (tid & 3) * 4;   // 0,4,8,12 : k offset

    float acc[4][4];
#pragma unroll
    for (int i = 0; i < 4; i++)
#pragma unroll
        for (int j = 0; j < 4; j++) acc[i][j] = 0.f;

    const float* Ap = &A[(m0 + lr) * K + lk];
    const float* Wp = &W[(n0 + lr) * K + lk];

    for (int k0 = 0; k0 < K; k0 += BK) {
        float4 av = *(const float4*)(Ap + k0);
        float4 wv = *(const float4*)(Wp + k0);
        As[lk + 0][lr] = av.x; As[lk + 1][lr] = av.y;
        As[lk + 2][lr] = av.z; As[lk + 3][lr] = av.w;
        Ws[lk + 0][lr] = wv.x; Ws[lk + 1][lr] = wv.y;
        Ws[lk + 2][lr] = wv.z; Ws[lk + 3][lr] = wv.w;
        __syncthreads();
#pragma unroll
        for (int kk = 0; kk < BK; kk++) {
            float4 a4 = *(const float4*)&As[kk][ty * 4];
            float4 b4 = *(const float4*)&Ws[kk][tx * 4];
            float ar[4] = {a4.x, a4.y, a4.z, a4.w};
            float br[4] = {b4.x, b4.y, b4.z, b4.w};
#pragma unroll
            for (int i = 0; i < 4; i++)
#pragma unroll
                for (int j = 0; j < 4; j++)
                    acc[i][j] = fmaf(ar[i], br[j], acc[i][j]);
        }
        __syncthreads();
    }

    const int nc = n0 + tx * 4;
    float4 bv = *(const float4*)&bias[nc];
    float bb[4] = {bv.x, bv.y, bv.z, bv.w};
#pragma unroll
    for (int i = 0; i < 4; i++) {
        const int m = m0 + ty * 4 + i;
        float4 o;
        float* op = &o.x;
#pragma unroll
        for (int j = 0; j < 4; j++) {
            float val = acc[i][j] + bb[j];
            if (FUSE_GELU) {
                float gl = 0.5f * val * (1.0f + erff(val * 0.70710678118654752f));
                val = g.res[m * N + nc + j] + gl;
            }
            op[j] = val;
        }
        *(float4*)&C[m * N + nc] = o;
    }
}

// ---------------- attention: h[b,i] += sum_j softmax_j(q_i k_j) v_j ----------------
__global__ __launch_bounds__(256) void attn_kernel(const float* __restrict__ q,
                                                   const float* __restrict__ k,
                                                   const float* __restrict__ v,
                                                   float* __restrict__ h) {
    const int b = blockIdx.x;
    __shared__ float k2s[Hd];
    __shared__ float vs[Hd];
    __shared__ float redmax[256];
    __shared__ float redmin[256];
    const int tid = threadIdx.x;
    const float LOG2E = 1.4426950408889634f;

    float lmax = -1e30f, lmin = 1e30f;
#pragma unroll
    for (int ii = 0; ii < Hd / 256; ii++) {
        int j = tid + ii * 256;
        float kk = k[b * Hd + j] * LOG2E;   // pre-scale: exp(x) = 2^(x*log2e)
        k2s[j] = kk;
        vs[j]  = v[b * Hd + j];
        lmax = fmaxf(lmax, kk);
        lmin = fminf(lmin, kk);
    }
    redmax[tid] = lmax;
    redmin[tid] = lmin;
    __syncthreads();
    for (int s = 128; s > 0; s >>= 1) {
        if (tid < s) {
            redmax[tid] = fmaxf(redmax[tid], redmax[tid + s]);
            redmin[tid] = fminf(redmin[tid], redmin[tid + s]);
        }
        __syncthreads();
    }
    const float kmax = redmax[0], kmin = redmin[0];

    // two output rows per thread, sharing the broadcast k/v LDS stream
    const float q0 = q[b * Hd + tid];
    const float q1 = q[b * Hd + tid + 256];
    const float m0 = (q0 >= 0.f) ? q0 * kmax : q0 * kmin;  // max_j q*k (log2 domain)
    const float m1 = (q1 >= 0.f) ? q1 * kmax : q1 * kmin;

    float d0 = 0.f, d1 = 0.f, n0 = 0.f, n1 = 0.f;
#pragma unroll 8
    for (int j = 0; j < Hd; j++) {
        float kv = k2s[j];
        float vv = vs[j];
        float e0 = ex2f(fmaf(q0, kv, -m0));
        float e1 = ex2f(fmaf(q1, kv, -m1));
        d0 += e0;
        d1 += e1;
        n0 = fmaf(e0, vv, n0);
        n1 = fmaf(e1, vv, n1);
    }
    h[b * Hd + tid]       += n0 / d0;
    h[b * Hd + tid + 256] += n1 / d1;
}

// ---------------- reg head: out[b] = fea[b,:]·reg_w + reg_b ----------------
__global__ __launch_bounds__(256) void reg_kernel(const float* __restrict__ fea,
                                                  const float* __restrict__ reg_w,
                                                  const float* __restrict__ reg_b,
                                                  float* __restrict__ out) {
    const int warp = (blockIdx.x * blockDim.x + threadIdx.x) >> 5;
    const int lane = threadIdx.x & 31;
    if (warp >= Bsz) return;
    float s = 0.f;
#pragma unroll
    for (int p = lane; p < Pd; p += 32)
        s = fmaf(fea[warp * Pd + p], reg_w[p], s);
#pragma unroll
    for (int o = 16; o; o >>= 1) s += __shfl_xor_sync(0xffffffffu, s, o);
    if (lane == 0) out[warp] = s + reg_b[0];
}

// ---------------- launcher ----------------
extern "C" void kernel_launch(void* const* d_in, const int* in_sizes, int n_in,
                              void* d_out, int out_size) {
    const float* x      = (const float*)d_in[0];
    const float* lin0_w = (const float*)d_in[1];
    const float* lin0_b = (const float*)d_in[2];
    const float* b1_qw = (const float*)d_in[3];  const float* b1_qb = (const float*)d_in[4];
    const float* b1_kw = (const float*)d_in[5];  const float* b1_kb = (const float*)d_in[6];
    const float* b1_vw = (const float*)d_in[7];  const float* b1_vb = (const float*)d_in[8];
    const float* b1_f1w = (const float*)d_in[9]; const float* b1_f1b = (const float*)d_in[10];
    const float* b2_qw = (const float*)d_in[11]; const float* b2_qb = (const float*)d_in[12];
    const float* b2_kw = (const float*)d_in[13]; const float* b2_kb = (const float*)d_in[14];
    const float* b2_vw = (const float*)d_in[15]; const float* b2_vb = (const float*)d_in[16];
    const float* b2_f1w = (const float*)d_in[17]; const float* b2_f1b = (const float*)d_in[18];
    const float* fea_w = (const float*)d_in[19]; const float* fea_b = (const float*)d_in[20];
    const float* reg_w = (const float*)d_in[21]; const float* reg_b = (const float*)d_in[22];

    float* out_scalar = (float*)d_out;           // [B]
    float* out_fea    = (float*)d_out + Bsz;     // [B, P]

    float *h0, *h1, *qb, *kb, *vb;
    cudaGetSymbolAddress((void**)&h0, g_h0);
    cudaGetSymbolAddress((void**)&h1, g_h1);
    cudaGetSymbolAddress((void**)&qb, g_q);
    cudaGetSymbolAddress((void**)&kb, g_k);
    cudaGetSymbolAddress((void**)&vb, g_v);

    const dim3 blk(256);

    // 1) h0 = x @ lin0_w^T + b
    {
        GemmArgs a{};
        a.A = x; a.W[0] = lin0_w; a.bias[0] = lin0_b; a.C[0] = h0;
        a.M = Bsz; a.N = Hd; a.K = INd;
        gemm_kernel<0><<<dim3(Hd / BN, Bsz / BM, 1), blk>>>(a);
    }

    // ---- block 1 (h0 -> h1) ----
    {
        GemmArgs a{};
        a.A = h0;
        a.W[0] = b1_qw; a.W[1] = b1_kw; a.W[2] = b1_vw;
        a.bias[0] = b1_qb; a.bias[1] = b1_kb; a.bias[2] = b1_vb;
        a.C[0] = qb; a.C[1] = kb; a.C[2] = vb;
        a.M = Bsz; a.N = Hd; a.K = Hd;
        gemm_kernel<0><<<dim3(Hd / BN, Bsz / BM, 3), blk>>>(a);
    }
    attn_kernel<<<Bsz, blk>>>(qb, kb, vb, h0);
    {
        GemmArgs a{};
        a.A = h0; a.W[0] = b1_f1w; a.bias[0] = b1_f1b; a.res = h0; a.C[0] = h1;
        a.M = Bsz; a.N = Hd; a.K = Hd;
        gemm_kernel<1><<<dim3(Hd / BN, Bsz / BM, 1), blk>>>(a);
    }

    // ---- block 2 (h1 -> h0) ----
    {
        GemmArgs a{};
        a.A = h1;
        a.W[0] = b2_qw; a.W[1] = b2_kw; a.W[2] = b2_vw;
        a.bias[0] = b2_qb; a.bias[1] = b2_kb; a.bias[2] = b2_vb;
        a.C[0] = qb; a.C[1] = kb; a.C[2] = vb;
        a.M = Bsz; a.N = Hd; a.K = Hd;
        gemm_kernel<0><<<dim3(Hd / BN, Bsz / BM, 3), blk>>>(a);
    }
    attn_kernel<<<Bsz, blk>>>(qb, kb, vb, h1);
    {
        GemmArgs a{};
        a.A = h1; a.W[0] = b2_f1w; a.bias[0] = b2_f1b; a.res = h1; a.C[0] = h0;
        a.M = Bsz; a.N = Hd; a.K = Hd;
        gemm_kernel<1><<<dim3(Hd / BN, Bsz / BM, 1), blk>>>(a);
    }

    // 4) fea = h0 @ fea_w^T + fea_b   (written straight into d_out)
    {
        GemmArgs a{};
        a.A = h0; a.W[0] = fea_w; a.bias[0] = fea_b; a.C[0] = out_fea;
        a.M = Bsz; a.N = Pd; a.K = Hd;
        gemm_kernel<0><<<dim3(Pd / BN, Bsz / BM, 1), blk>>>(a);
    }

    // 5) out[b] = fea[b,:]·reg_w + reg_b
    reg_kernel<<<(Bsz * 32) / 256, blk>>>(out_fea, reg_w, reg_b, out_scalar);
}